// round 12
// baseline (speedup 1.0000x reference)
#include <cuda_runtime.h>
#include <cuda_bf16.h>
#include <cstdint>

#define N_ROWS   16384
#define C_DIM    64
#define O_CODES  8192
#define MROWS    128          // rows per CTA
#define NCHUNK   64           // codes per chunk
#define KSPLIT   4
#define CH_PER_CTA (O_CODES / NCHUNK / KSPLIT)   // 32
#define CMAX     128
#define THREADS  256          // 8 warps, 16 rows each

#define A_BYTES  (MROWS * C_DIM * 2)           // 16384
#define B_BYTES  (NCHUNK * C_DIM * 2)          // 8192
#define B_OFF(b) (A_BYTES + (b) * B_BYTES)
#define SMEM_TOTAL (A_BYTES + 2 * B_BYTES)     // 32 KB

// Scratch (__device__ globals; no allocation allowed)
__device__ float              g_xx[N_ROWS];
__device__ float              g_xlnorm[N_ROWS];
__device__ float              g_ww[O_CODES];
__device__ __nv_bfloat16      g_xh[N_ROWS * C_DIM];
__device__ __nv_bfloat16      g_wh[O_CODES * C_DIM];
__device__ unsigned           g_wmax_bits;     // max_k ||w_k||   (atomicMax, monotone)
__device__ unsigned           g_wlmax_bits;    // max_k ||w_lo,k||
__device__ int                g_cnt[N_ROWS];
__device__ int                g_cand[N_ROWS * CMAX];
__device__ unsigned long long g_best[N_ROWS];
__device__ double             g_acc[3];

// ---------------------------------------------------------------------------
__device__ __forceinline__ uint32_t smem_u32(const void* p) {
    uint32_t a;
    asm("{ .reg .u64 t; cvta.to.shared.u64 t, %1; cvt.u32.u64 %0, t; }"
        : "=r"(a) : "l"(p));
    return a;
}
// SW128 atom layout for a [rows x 64 bf16] tile: atom = 8 rows x 128B.
__device__ __forceinline__ uint32_t tile_off(int row, int j0) {
    uint32_t b = (uint32_t)((row >> 3) * 1024 + (row & 7) * 128 + j0 * 2);
    return b ^ ((b >> 3) & 0x70);
}
__device__ __forceinline__ void ldsm_x4(uint32_t* r, uint32_t addr) {
    asm volatile("ldmatrix.sync.aligned.m8n8.x4.shared.b16 {%0,%1,%2,%3}, [%4];"
        : "=r"(r[0]), "=r"(r[1]), "=r"(r[2]), "=r"(r[3]) : "r"(addr));
}
__device__ __forceinline__ void mma16816(float* c, const uint32_t* a,
                                         uint32_t b0, uint32_t b1) {
    asm volatile("mma.sync.aligned.m16n8k16.row.col.f32.bf16.bf16.f32 "
        "{%0,%1,%2,%3}, {%4,%5,%6,%7}, {%8,%9}, {%0,%1,%2,%3};"
        : "+f"(c[0]), "+f"(c[1]), "+f"(c[2]), "+f"(c[3])
        : "r"(a[0]), "r"(a[1]), "r"(a[2]), "r"(a[3]), "r"(b0), "r"(b1));
}
// bf16 hi-pack of (a,b); accumulates squared lo-residual into sq.
__device__ __forceinline__ uint32_t pack2(float a, float b, float& sq) {
    __nv_bfloat16 ha = __float2bfloat16(a), hb = __float2bfloat16(b);
    float la = __fsub_rn(a, __bfloat162float(ha));
    float lb = __fsub_rn(b, __bfloat162float(hb));
    sq = fmaf(la, la, fmaf(lb, lb, sq));
    return (uint32_t)__bfloat16_as_ushort(ha) |
           ((uint32_t)__bfloat16_as_ushort(hb) << 16);
}

// ---------------------------------------------------------------------------
// Kernel A: norms (exact fmaf chain), bf16-hi conversion, residual norms,
// global max code norms (atomicMax on positive-float bits), resets.
// ---------------------------------------------------------------------------
__global__ void prep_kernel(const float* __restrict__ latents,
                            const float* __restrict__ codebook) {
    int t = blockIdx.x * blockDim.x + threadIdx.x;
    if (t == 0) { g_acc[0] = 0.0; g_acc[1] = 0.0; g_acc[2] = 0.0; }
    if (t < N_ROWS) {
        const float4* p = reinterpret_cast<const float4*>(latents + (size_t)t * C_DIM);
        uint4* dst = reinterpret_cast<uint4*>(g_xh + (size_t)t * C_DIM);
        float s = 0.f, lsq = 0.f;
        #pragma unroll
        for (int q = 0; q < 8; q++) {
            float4 v0 = p[2 * q], v1 = p[2 * q + 1];
            s = fmaf(v0.x, v0.x, s); s = fmaf(v0.y, v0.y, s);
            s = fmaf(v0.z, v0.z, s); s = fmaf(v0.w, v0.w, s);
            s = fmaf(v1.x, v1.x, s); s = fmaf(v1.y, v1.y, s);
            s = fmaf(v1.z, v1.z, s); s = fmaf(v1.w, v1.w, s);
            uint4 o;
            o.x = pack2(v0.x, v0.y, lsq);
            o.y = pack2(v0.z, v0.w, lsq);
            o.z = pack2(v1.x, v1.y, lsq);
            o.w = pack2(v1.z, v1.w, lsq);
            dst[q] = o;
        }
        g_xx[t] = s;
        g_xlnorm[t] = sqrtf(lsq) * 1.0001f;
        g_cnt[t] = 0;
    } else if (t < N_ROWS + O_CODES) {
        int k = t - N_ROWS;
        const float4* p = reinterpret_cast<const float4*>(codebook + (size_t)k * C_DIM);
        uint4* dst = reinterpret_cast<uint4*>(g_wh + (size_t)k * C_DIM);
        float s = 0.f, lsq = 0.f;
        #pragma unroll
        for (int q = 0; q < 8; q++) {
            float4 v0 = p[2 * q], v1 = p[2 * q + 1];
            s = fmaf(v0.x, v0.x, s); s = fmaf(v0.y, v0.y, s);
            s = fmaf(v0.z, v0.z, s); s = fmaf(v0.w, v0.w, s);
            s = fmaf(v1.x, v1.x, s); s = fmaf(v1.y, v1.y, s);
            s = fmaf(v1.z, v1.z, s); s = fmaf(v1.w, v1.w, s);
            uint4 o;
            o.x = pack2(v0.x, v0.y, lsq);
            o.y = pack2(v0.z, v0.w, lsq);
            o.z = pack2(v1.x, v1.y, lsq);
            o.w = pack2(v1.z, v1.w, lsq);
            dst[q] = o;
        }
        g_ww[k] = s;
        atomicMax(&g_wmax_bits,  __float_as_uint(sqrtf(s)   * 1.0001f));
        atomicMax(&g_wlmax_bits, __float_as_uint(sqrtf(lsq) * 1.0001f));
    }
}

// ---------------------------------------------------------------------------
// B-chunk staging via cp.async (16B). 512 units / 256 threads = 2 per thread.
// ---------------------------------------------------------------------------
__device__ __forceinline__ void stage_b(unsigned char* smem, int chunk, int buf,
                                        int tid) {
    uint32_t dstBase = smem_u32(smem) + B_OFF(buf);
    #pragma unroll
    for (int t = 0; t < 2; t++) {
        int idx = tid + THREADS * t;    // 0..511
        int n = idx >> 3, j0 = (idx & 7) * 8;
        const __nv_bfloat16* src = g_wh + (size_t)(chunk * NCHUNK + n) * C_DIM + j0;
        uint32_t dst = dstBase + tile_off(n, j0);
        asm volatile("cp.async.cg.shared.global [%0], [%1], 16;"
                     :: "r"(dst), "l"(src) : "memory");
    }
    asm volatile("cp.async.commit_group;" ::: "memory");
}

// ---------------------------------------------------------------------------
// Kernel B: bf16-hi GEMM sweep (mma.sync) + candidate emission.
//   Grid = (row-blocks) x KSPLIT; blockIdx.y picks a 2048-code span.
//   8 warps x 16 rows, chunks of 64 codes, K=64 (4 mma K-steps), 3 CTAs/SM.
//   eps_row = 2*(||x_lo||*Wmax + ||x_hi||*WLmax) + 2e-5 (Cauchy-Schwarz,
//   rigorous superset of exact-argmin + ties; per-split window still superset).
// ---------------------------------------------------------------------------
__global__ void __launch_bounds__(THREADS, 3)
sweep_kernel() {
    extern __shared__ unsigned char smem[];
    const uint32_t sb = smem_u32(smem);
    const int tid = threadIdx.x, lane = tid & 31, wid = tid >> 5;
    const int rowBase = blockIdx.x * MROWS;
    const int chunkBase = blockIdx.y * CH_PER_CTA;

    // Stage A tile (128 rows x 64 bf16)
    #pragma unroll
    for (int t = 0; t < 4; t++) {
        int idx = tid + THREADS * t;
        int r = idx >> 3, j0 = (idx & 7) * 8;
        *reinterpret_cast<uint4*>(smem + tile_off(r, j0)) =
            *reinterpret_cast<const uint4*>(g_xh + (size_t)(rowBase + r) * C_DIM + j0);
    }

    // ldmatrix per-lane address constants
    const int g = lane >> 3;                        // 8-lane group 0..3
    const int arow = 16 * wid + 8 * (g & 1) + (lane & 7);
    const uint32_t ax = (uint32_t)(arow & 7) * 16;
    const uint32_t aB = sb + (uint32_t)(arow >> 3) * 1024 + (arow & 7) * 128;
    const int kA = 8 * (g >> 1);
    const int bcr = 8 * (g >> 1) + (lane & 7);      // B n-row within 16-pair
    const uint32_t bAtom = (uint32_t)(bcr >> 3) * 1024 + (bcr & 7) * 128;
    const uint32_t bx = (uint32_t)(bcr & 7) * 16;
    const int kB = 8 * (g & 1);

    const int row0 = rowBase + 16 * wid + (lane >> 2);  // rows row0, row0+8
    const float Wmax  = __uint_as_float(g_wmax_bits);
    const float WLmax = __uint_as_float(g_wlmax_bits);
    float run[2], thr[2], eps[2];
    #pragma unroll
    for (int q = 0; q < 2; q++) {
        int r = row0 + 8 * q;
        float xln = g_xlnorm[r];
        float xhn = sqrtf(g_xx[r]) * 1.0001f + xln;
        eps[q] = 2.f * (xln * Wmax + xhn * WLmax) + 2e-5f;
        run[q] = -3.4e38f; thr[q] = -3.4e38f;
    }

    stage_b(smem, chunkBase, 0, tid);

    for (int ci = 0; ci < CH_PER_CTA; ci++) {
        const int i = chunkBase + ci;
        if (ci + 1 < CH_PER_CTA) {
            stage_b(smem, i + 1, (ci + 1) & 1, tid);
            asm volatile("cp.async.wait_group 1;" ::: "memory");
        } else {
            asm volatile("cp.async.wait_group 0;" ::: "memory");
        }
        __syncthreads();

        const uint32_t sbB = sb + B_OFF(ci & 1);
        float acc[8][4];
        #pragma unroll
        for (int nt = 0; nt < 8; nt++)
            #pragma unroll
            for (int q = 0; q < 4; q++) acc[nt][q] = 0.f;

        #pragma unroll
        for (int ks = 0; ks < 4; ks++) {
            uint32_t a0r[4];
            ldsm_x4(a0r, aB + (((uint32_t)((ks * 16 + kA) * 2)) ^ ax));
            uint32_t bb = sbB + bAtom + (((uint32_t)((ks * 16 + kB) * 2)) ^ bx);
            #pragma unroll
            for (int np = 0; np < 4; np++) {
                uint32_t br[4];
                ldsm_x4(br, bb + np * 2048);          // non-trans: B is [n][k]
                mma16816(acc[2 * np],     a0r, br[0], br[1]);
                mma16816(acc[2 * np + 1], a0r, br[2], br[3]);
            }
        }

        // Candidate emission. D-frag: c0,c1 -> row lane/4, c2,c3 -> +8,
        // cols = nt*8 + 2*(lane%4) + {0,1}.
        const int colBase = i * NCHUNK + 2 * (lane & 3);
        #pragma unroll
        for (int nt = 0; nt < 8; nt++) {
            #pragma unroll
            for (int q = 0; q < 2; q++) {
                float v0 = acc[nt][2 * q], v1 = acc[nt][2 * q + 1];
                if (fmaxf(v0, v1) >= thr[q]) {
                    int row = row0 + 8 * q;
                    #pragma unroll
                    for (int j = 0; j < 2; j++) {
                        float v = j ? v1 : v0;
                        if (v >= thr[q]) {
                            if (v > run[q]) { run[q] = v; thr[q] = v - eps[q]; }
                            int slot = atomicAdd(&g_cnt[row], 1);
                            if (slot < CMAX)
                                g_cand[row * CMAX + slot] = colBase + nt * 8 + j;
                        }
                    }
                }
            }
        }
        // Cross-lane max (lanes with equal lane>>2 share rows).
        #pragma unroll
        for (int q = 0; q < 2; q++) {
            run[q] = fmaxf(run[q], __shfl_xor_sync(0xffffffffu, run[q], 1));
            run[q] = fmaxf(run[q], __shfl_xor_sync(0xffffffffu, run[q], 2));
            thr[q] = run[q] - eps[q];
        }
        __syncthreads();
    }
}

// ---------------------------------------------------------------------------
// Kernel C: exact recheck over candidates (bit-identical chain that passed).
// ---------------------------------------------------------------------------
__global__ void __launch_bounds__(256)
pass2_kernel(const float* __restrict__ latents,
             const float* __restrict__ codebook) {
    const int lane = threadIdx.x & 31, wid = threadIdx.x >> 5;
    const int row = blockIdx.x * 8 + wid;
    const int cnt = g_cnt[row];
    const float xx = g_xx[row];
    const float4* xp = reinterpret_cast<const float4*>(latents + (size_t)row * C_DIM);
    unsigned long long key = 0xffffffffffffffffull;

    if (cnt <= CMAX) {
        for (int ci = lane; ci < cnt; ci += 32) {
            int k = g_cand[row * CMAX + ci];
            const float4* w = reinterpret_cast<const float4*>(codebook + (size_t)k * C_DIM);
            float acc = 0.f;
            #pragma unroll
            for (int q = 0; q < 16; q++) {
                float4 a = xp[q], b = w[q];
                acc = fmaf(a.x, b.x, acc); acc = fmaf(a.y, b.y, acc);
                acc = fmaf(a.z, b.z, acc); acc = fmaf(a.w, b.w, acc);
            }
            float d = __fsub_rn(__fadd_rn(xx, g_ww[k]), __fmul_rn(2.0f, acc));
            unsigned long long kk =
                ((unsigned long long)__float_as_uint(d) << 32) | (unsigned)k;
            if (kk < key) key = kk;
        }
    } else {
        // safety fallback: full exact scan for this row
        for (int k = lane; k < O_CODES; k += 32) {
            const float4* w = reinterpret_cast<const float4*>(codebook + (size_t)k * C_DIM);
            float acc = 0.f;
            #pragma unroll
            for (int q = 0; q < 16; q++) {
                float4 a = xp[q], b = w[q];
                acc = fmaf(a.x, b.x, acc); acc = fmaf(a.y, b.y, acc);
                acc = fmaf(a.z, b.z, acc); acc = fmaf(a.w, b.w, acc);
            }
            float d = __fsub_rn(__fadd_rn(xx, g_ww[k]), __fmul_rn(2.0f, acc));
            unsigned long long kk =
                ((unsigned long long)__float_as_uint(d) << 32) | (unsigned)k;
            if (kk < key) key = kk;
        }
    }
    #pragma unroll
    for (int o = 16; o > 0; o >>= 1) {
        unsigned long long ok = __shfl_down_sync(0xffffffffu, key, o);
        if (ok < key) key = ok;
    }
    if (lane == 0) g_best[row] = key;
}

// ---------------------------------------------------------------------------
// Kernel D: gather + straight-through output + loss sums, float4-vectorized.
// Grid sized so each thread handles exactly one float4 (no loop iterations).
// Per-element fp32 op chain identical to the scalar (passing) version.
// ---------------------------------------------------------------------------
__global__ void epilogue_kernel(const float* __restrict__ latents,
                                const float* __restrict__ y,
                                const float* __restrict__ codebook,
                                const float* __restrict__ noise,
                                float* __restrict__ out, int nElems) {
    double s0 = 0.0, s1 = 0.0, s2 = 0.0;
    const int nVec = nElems >> 2;
    int stride = gridDim.x * blockDim.x;
    for (int v = blockIdx.x * blockDim.x + threadIdx.x; v < nVec; v += stride) {
        int e = v << 2;
        int i = e >> 6, c = e & 63;
        float4 lat = *reinterpret_cast<const float4*>(latents + e);
        float4 yv  = *reinterpret_cast<const float4*>(y + e);
        int kd = (int)(g_best[i] & 0xffffffffull);
        int off = (int)rintf(__fmul_rn(noise[i], 0.5f));
        int kn = kd + off;
        kn = kn < 0 ? 0 : (kn > O_CODES - 1 ? O_CODES - 1 : kn);
        float4 qd = *reinterpret_cast<const float4*>(codebook + (kd << 6) + c);
        float4 qn = *reinterpret_cast<const float4*>(codebook + (kn << 6) + c);
        float4 ov;
        {
            float diff, r, cm;
            diff = __fsub_rn(qn.x, lat.x); ov.x = __fadd_rn(lat.x, diff);
            r = __fsub_rn(ov.x, yv.x); cm = __fsub_rn(lat.x, qd.x);
            s0 += (double)r * r; s1 += (double)cm * cm; s2 += (double)diff * diff;
            diff = __fsub_rn(qn.y, lat.y); ov.y = __fadd_rn(lat.y, diff);
            r = __fsub_rn(ov.y, yv.y); cm = __fsub_rn(lat.y, qd.y);
            s0 += (double)r * r; s1 += (double)cm * cm; s2 += (double)diff * diff;
            diff = __fsub_rn(qn.z, lat.z); ov.z = __fadd_rn(lat.z, diff);
            r = __fsub_rn(ov.z, yv.z); cm = __fsub_rn(lat.z, qd.z);
            s0 += (double)r * r; s1 += (double)cm * cm; s2 += (double)diff * diff;
            diff = __fsub_rn(qn.w, lat.w); ov.w = __fadd_rn(lat.w, diff);
            r = __fsub_rn(ov.w, yv.w); cm = __fsub_rn(lat.w, qd.w);
            s0 += (double)r * r; s1 += (double)cm * cm; s2 += (double)diff * diff;
        }
        *reinterpret_cast<float4*>(out + e) = ov;
    }
    #pragma unroll
    for (int o = 16; o > 0; o >>= 1) {
        s0 += __shfl_down_sync(0xffffffffu, s0, o);
        s1 += __shfl_down_sync(0xffffffffu, s1, o);
        s2 += __shfl_down_sync(0xffffffffu, s2, o);
    }
    if ((threadIdx.x & 31) == 0) {
        atomicAdd(&g_acc[0], s0);
        atomicAdd(&g_acc[1], s1);
        atomicAdd(&g_acc[2], s2);
    }
}

__global__ void finish_kernel(float* __restrict__ out, int lossStart, int lossEnd) {
    double n = (double)N_ROWS * (double)C_DIM;
    float loss = (float)(g_acc[0] / n + 0.25 * (g_acc[1] / n) + g_acc[2] / n);
    for (int i = lossStart + (int)threadIdx.x; i < lossEnd; i += blockDim.x) out[i] = loss;
}

// ---------------------------------------------------------------------------
extern "C" void kernel_launch(void* const* d_in, const int* in_sizes, int n_in,
                              void* d_out, int out_size) {
    const float* latents  = (const float*)d_in[0];
    const float* y        = (const float*)d_in[1];
    const float* codebook = (const float*)d_in[2];
    const float* noise    = (const float*)d_in[3];
    float* out = (float*)d_out;
    int nElems = in_sizes[0];   // 1048576

    cudaFuncSetAttribute(sweep_kernel,
                         cudaFuncAttributeMaxDynamicSharedMemorySize, SMEM_TOTAL);

    prep_kernel<<<(N_ROWS + O_CODES + 255) / 256, 256>>>(latents, codebook);
    dim3 sg(N_ROWS / MROWS, KSPLIT);
    sweep_kernel<<<sg, THREADS, SMEM_TOTAL>>>();
    pass2_kernel<<<N_ROWS / 8, 256>>>(latents, codebook);
    epilogue_kernel<<<1024, 256>>>(latents, y, codebook, noise, out, nElems);
    if (out_size > nElems) finish_kernel<<<1, 32>>>(out, nElems, out_size);
}

// round 13
// speedup vs baseline: 1.2880x; 1.2880x over previous
#include <cuda_runtime.h>
#include <cuda_bf16.h>
#include <cstdint>

#define N_ROWS   16384
#define C_DIM    64
#define O_CODES  8192
#define MROWS    128          // rows per CTA
#define NCHUNK   128          // codes per chunk
#define KSPLIT   2
#define CH_PER_CTA (O_CODES / NCHUNK / KSPLIT)   // 32
#define CMAX     128
#define THREADS  256          // 8 warps, 16 rows each

#define A_BYTES  (MROWS * C_DIM * 2)           // 16384
#define B_BYTES  (NCHUNK * C_DIM * 2)          // 16384
#define B_OFF(b) (A_BYTES + (b) * B_BYTES)
#define SMEM_TOTAL (A_BYTES + 2 * B_BYTES)     // 48 KB

// Scratch (__device__ globals; no allocation allowed)
__device__ float              g_xx[N_ROWS];
__device__ float              g_xlnorm[N_ROWS];
__device__ float              g_ww[O_CODES];
__device__ __nv_bfloat16      g_xh[N_ROWS * C_DIM];
__device__ __nv_bfloat16      g_wh[O_CODES * C_DIM];
__device__ unsigned           g_wmax_bits;     // max_k ||w_k||   (atomicMax, monotone)
__device__ unsigned           g_wlmax_bits;    // max_k ||w_lo,k||
__device__ int                g_cnt[N_ROWS];
__device__ int                g_cand[N_ROWS * CMAX];
__device__ unsigned long long g_best[N_ROWS];
__device__ double             g_acc[3];

// ---------------------------------------------------------------------------
__device__ __forceinline__ uint32_t smem_u32(const void* p) {
    uint32_t a;
    asm("{ .reg .u64 t; cvta.to.shared.u64 t, %1; cvt.u32.u64 %0, t; }"
        : "=r"(a) : "l"(p));
    return a;
}
// SW128 atom layout for a [rows x 64 bf16] tile: atom = 8 rows x 128B.
__device__ __forceinline__ uint32_t tile_off(int row, int j0) {
    uint32_t b = (uint32_t)((row >> 3) * 1024 + (row & 7) * 128 + j0 * 2);
    return b ^ ((b >> 3) & 0x70);
}
__device__ __forceinline__ void ldsm_x4(uint32_t* r, uint32_t addr) {
    asm volatile("ldmatrix.sync.aligned.m8n8.x4.shared.b16 {%0,%1,%2,%3}, [%4];"
        : "=r"(r[0]), "=r"(r[1]), "=r"(r[2]), "=r"(r[3]) : "r"(addr));
}
__device__ __forceinline__ void mma16816(float* c, const uint32_t* a,
                                         uint32_t b0, uint32_t b1) {
    asm volatile("mma.sync.aligned.m16n8k16.row.col.f32.bf16.bf16.f32 "
        "{%0,%1,%2,%3}, {%4,%5,%6,%7}, {%8,%9}, {%0,%1,%2,%3};"
        : "+f"(c[0]), "+f"(c[1]), "+f"(c[2]), "+f"(c[3])
        : "r"(a[0]), "r"(a[1]), "r"(a[2]), "r"(a[3]), "r"(b0), "r"(b1));
}
// bf16 hi-pack of (a,b); accumulates squared lo-residual into sq.
__device__ __forceinline__ uint32_t pack2(float a, float b, float& sq) {
    __nv_bfloat16 ha = __float2bfloat16(a), hb = __float2bfloat16(b);
    float la = __fsub_rn(a, __bfloat162float(ha));
    float lb = __fsub_rn(b, __bfloat162float(hb));
    sq = fmaf(la, la, fmaf(lb, lb, sq));
    return (uint32_t)__bfloat16_as_ushort(ha) |
           ((uint32_t)__bfloat16_as_ushort(hb) << 16);
}

// ---------------------------------------------------------------------------
// Kernel A: norms (exact fmaf chain), bf16-hi conversion, residual norms,
// global max code norms (atomicMax on positive-float bits), resets.
// ---------------------------------------------------------------------------
__global__ void prep_kernel(const float* __restrict__ latents,
                            const float* __restrict__ codebook) {
    int t = blockIdx.x * blockDim.x + threadIdx.x;
    if (t == 0) { g_acc[0] = 0.0; g_acc[1] = 0.0; g_acc[2] = 0.0; }
    if (t < N_ROWS) {
        const float4* p = reinterpret_cast<const float4*>(latents + (size_t)t * C_DIM);
        uint4* dst = reinterpret_cast<uint4*>(g_xh + (size_t)t * C_DIM);
        float s = 0.f, lsq = 0.f;
        #pragma unroll
        for (int q = 0; q < 8; q++) {
            float4 v0 = p[2 * q], v1 = p[2 * q + 1];
            s = fmaf(v0.x, v0.x, s); s = fmaf(v0.y, v0.y, s);
            s = fmaf(v0.z, v0.z, s); s = fmaf(v0.w, v0.w, s);
            s = fmaf(v1.x, v1.x, s); s = fmaf(v1.y, v1.y, s);
            s = fmaf(v1.z, v1.z, s); s = fmaf(v1.w, v1.w, s);
            uint4 o;
            o.x = pack2(v0.x, v0.y, lsq);
            o.y = pack2(v0.z, v0.w, lsq);
            o.z = pack2(v1.x, v1.y, lsq);
            o.w = pack2(v1.z, v1.w, lsq);
            dst[q] = o;
        }
        g_xx[t] = s;
        g_xlnorm[t] = sqrtf(lsq) * 1.0001f;
        g_cnt[t] = 0;
    } else if (t < N_ROWS + O_CODES) {
        int k = t - N_ROWS;
        const float4* p = reinterpret_cast<const float4*>(codebook + (size_t)k * C_DIM);
        uint4* dst = reinterpret_cast<uint4*>(g_wh + (size_t)k * C_DIM);
        float s = 0.f, lsq = 0.f;
        #pragma unroll
        for (int q = 0; q < 8; q++) {
            float4 v0 = p[2 * q], v1 = p[2 * q + 1];
            s = fmaf(v0.x, v0.x, s); s = fmaf(v0.y, v0.y, s);
            s = fmaf(v0.z, v0.z, s); s = fmaf(v0.w, v0.w, s);
            s = fmaf(v1.x, v1.x, s); s = fmaf(v1.y, v1.y, s);
            s = fmaf(v1.z, v1.z, s); s = fmaf(v1.w, v1.w, s);
            uint4 o;
            o.x = pack2(v0.x, v0.y, lsq);
            o.y = pack2(v0.z, v0.w, lsq);
            o.z = pack2(v1.x, v1.y, lsq);
            o.w = pack2(v1.z, v1.w, lsq);
            dst[q] = o;
        }
        g_ww[k] = s;
        atomicMax(&g_wmax_bits,  __float_as_uint(sqrtf(s)   * 1.0001f));
        atomicMax(&g_wlmax_bits, __float_as_uint(sqrtf(lsq) * 1.0001f));
    }
}

// ---------------------------------------------------------------------------
// B-chunk staging via cp.async (16B). 1024 units / 256 threads = 4 per thread.
// ---------------------------------------------------------------------------
__device__ __forceinline__ void stage_b(unsigned char* smem, int chunk, int buf,
                                        int tid) {
    uint32_t dstBase = smem_u32(smem) + B_OFF(buf);
    #pragma unroll
    for (int t = 0; t < 4; t++) {
        int idx = tid + THREADS * t;    // 0..1023
        int n = idx >> 3, j0 = (idx & 7) * 8;
        const __nv_bfloat16* src = g_wh + (size_t)(chunk * NCHUNK + n) * C_DIM + j0;
        uint32_t dst = dstBase + tile_off(n, j0);
        asm volatile("cp.async.cg.shared.global [%0], [%1], 16;"
                     :: "r"(dst), "l"(src) : "memory");
    }
    asm volatile("cp.async.commit_group;" ::: "memory");
}

// ---------------------------------------------------------------------------
// Kernel B: bf16-hi GEMM sweep (mma.sync) + candidate emission.
//   Grid = (row-blocks) x KSPLIT; blockIdx.y picks a 4096-code span.
//   8 warps x 16 rows, chunks of 128 codes, K=64 (4 mma K-steps), 2 CTAs/SM.
//   A fragments hoisted out of the chunk loop (A tile is chunk-invariant).
//   eps_row = 2*(||x_lo||*Wmax + ||x_hi||*WLmax) + 2e-5 (Cauchy-Schwarz,
//   rigorous superset of exact-argmin + ties; per-split window still superset).
// ---------------------------------------------------------------------------
__global__ void __launch_bounds__(THREADS, 2)
sweep_kernel() {
    extern __shared__ unsigned char smem[];
    const uint32_t sb = smem_u32(smem);
    const int tid = threadIdx.x, lane = tid & 31, wid = tid >> 5;
    const int rowBase = blockIdx.x * MROWS;
    const int chunkBase = blockIdx.y * CH_PER_CTA;

    // Stage A tile (128 rows x 64 bf16)
    #pragma unroll
    for (int t = 0; t < 4; t++) {
        int idx = tid + THREADS * t;
        int r = idx >> 3, j0 = (idx & 7) * 8;
        *reinterpret_cast<uint4*>(smem + tile_off(r, j0)) =
            *reinterpret_cast<const uint4*>(g_xh + (size_t)(rowBase + r) * C_DIM + j0);
    }

    // ldmatrix per-lane address constants
    const int g = lane >> 3;                        // 8-lane group 0..3
    const int arow = 16 * wid + 8 * (g & 1) + (lane & 7);
    const uint32_t ax = (uint32_t)(arow & 7) * 16;
    const uint32_t aB = sb + (uint32_t)(arow >> 3) * 1024 + (arow & 7) * 128;
    const int kA = 8 * (g >> 1);
    const int bcr = 8 * (g >> 1) + (lane & 7);      // B n-row within 16-pair
    const uint32_t bAtom = (uint32_t)(bcr >> 3) * 1024 + (bcr & 7) * 128;
    const uint32_t bx = (uint32_t)(bcr & 7) * 16;
    const int kB = 8 * (g & 1);

    const int row0 = rowBase + 16 * wid + (lane >> 2);  // rows row0, row0+8
    const float Wmax  = __uint_as_float(g_wmax_bits);
    const float WLmax = __uint_as_float(g_wlmax_bits);
    float run[2], thr[2], eps[2];
    #pragma unroll
    for (int q = 0; q < 2; q++) {
        int r = row0 + 8 * q;
        float xln = g_xlnorm[r];
        float xhn = sqrtf(g_xx[r]) * 1.0001f + xln;
        eps[q] = 2.f * (xln * Wmax + xhn * WLmax) + 2e-5f;
        run[q] = -3.4e38f; thr[q] = -3.4e38f;
    }

    stage_b(smem, chunkBase, 0, tid);

    // A staged with plain stores above; sync before ldmatrix reads it.
    __syncthreads();

    // Hoisted A fragments: invariant across all chunks (16 regs).
    uint32_t aFrag[4][4];
    #pragma unroll
    for (int ks = 0; ks < 4; ks++)
        ldsm_x4(aFrag[ks], aB + (((uint32_t)((ks * 16 + kA) * 2)) ^ ax));

    for (int ci = 0; ci < CH_PER_CTA; ci++) {
        const int i = chunkBase + ci;
        if (ci + 1 < CH_PER_CTA) {
            stage_b(smem, i + 1, (ci + 1) & 1, tid);
            asm volatile("cp.async.wait_group 1;" ::: "memory");
        } else {
            asm volatile("cp.async.wait_group 0;" ::: "memory");
        }
        __syncthreads();

        const uint32_t sbB = sb + B_OFF(ci & 1);
        float acc[16][4];
        #pragma unroll
        for (int nt = 0; nt < 16; nt++)
            #pragma unroll
            for (int q = 0; q < 4; q++) acc[nt][q] = 0.f;

        #pragma unroll
        for (int ks = 0; ks < 4; ks++) {
            uint32_t bb = sbB + bAtom + (((uint32_t)((ks * 16 + kB) * 2)) ^ bx);
            #pragma unroll
            for (int np = 0; np < 8; np++) {
                uint32_t br[4];
                ldsm_x4(br, bb + np * 2048);          // non-trans: B is [n][k]
                mma16816(acc[2 * np],     aFrag[ks], br[0], br[1]);
                mma16816(acc[2 * np + 1], aFrag[ks], br[2], br[3]);
            }
        }

        // Candidate emission. D-frag: c0,c1 -> row lane/4, c2,c3 -> +8,
        // cols = nt*8 + 2*(lane%4) + {0,1}.
        const int colBase = i * NCHUNK + 2 * (lane & 3);
        #pragma unroll
        for (int nt = 0; nt < 16; nt++) {
            #pragma unroll
            for (int q = 0; q < 2; q++) {
                float v0 = acc[nt][2 * q], v1 = acc[nt][2 * q + 1];
                if (fmaxf(v0, v1) >= thr[q]) {
                    int row = row0 + 8 * q;
                    #pragma unroll
                    for (int j = 0; j < 2; j++) {
                        float v = j ? v1 : v0;
                        if (v >= thr[q]) {
                            if (v > run[q]) { run[q] = v; thr[q] = v - eps[q]; }
                            int slot = atomicAdd(&g_cnt[row], 1);
                            if (slot < CMAX)
                                g_cand[row * CMAX + slot] = colBase + nt * 8 + j;
                        }
                    }
                }
            }
        }
        // Cross-lane max (lanes with equal lane>>2 share rows).
        #pragma unroll
        for (int q = 0; q < 2; q++) {
            run[q] = fmaxf(run[q], __shfl_xor_sync(0xffffffffu, run[q], 1));
            run[q] = fmaxf(run[q], __shfl_xor_sync(0xffffffffu, run[q], 2));
            thr[q] = run[q] - eps[q];
        }
        __syncthreads();
    }
}

// ---------------------------------------------------------------------------
// Kernel C: exact recheck over candidates (bit-identical chain that passed).
// ---------------------------------------------------------------------------
__global__ void __launch_bounds__(256)
pass2_kernel(const float* __restrict__ latents,
             const float* __restrict__ codebook) {
    const int lane = threadIdx.x & 31, wid = threadIdx.x >> 5;
    const int row = blockIdx.x * 8 + wid;
    const int cnt = g_cnt[row];
    const float xx = g_xx[row];
    const float4* xp = reinterpret_cast<const float4*>(latents + (size_t)row * C_DIM);
    unsigned long long key = 0xffffffffffffffffull;

    if (cnt <= CMAX) {
        for (int ci = lane; ci < cnt; ci += 32) {
            int k = g_cand[row * CMAX + ci];
            const float4* w = reinterpret_cast<const float4*>(codebook + (size_t)k * C_DIM);
            float acc = 0.f;
            #pragma unroll
            for (int q = 0; q < 16; q++) {
                float4 a = xp[q], b = w[q];
                acc = fmaf(a.x, b.x, acc); acc = fmaf(a.y, b.y, acc);
                acc = fmaf(a.z, b.z, acc); acc = fmaf(a.w, b.w, acc);
            }
            float d = __fsub_rn(__fadd_rn(xx, g_ww[k]), __fmul_rn(2.0f, acc));
            unsigned long long kk =
                ((unsigned long long)__float_as_uint(d) << 32) | (unsigned)k;
            if (kk < key) key = kk;
        }
    } else {
        // safety fallback: full exact scan for this row
        for (int k = lane; k < O_CODES; k += 32) {
            const float4* w = reinterpret_cast<const float4*>(codebook + (size_t)k * C_DIM);
            float acc = 0.f;
            #pragma unroll
            for (int q = 0; q < 16; q++) {
                float4 a = xp[q], b = w[q];
                acc = fmaf(a.x, b.x, acc); acc = fmaf(a.y, b.y, acc);
                acc = fmaf(a.z, b.z, acc); acc = fmaf(a.w, b.w, acc);
            }
            float d = __fsub_rn(__fadd_rn(xx, g_ww[k]), __fmul_rn(2.0f, acc));
            unsigned long long kk =
                ((unsigned long long)__float_as_uint(d) << 32) | (unsigned)k;
            if (kk < key) key = kk;
        }
    }
    #pragma unroll
    for (int o = 16; o > 0; o >>= 1) {
        unsigned long long ok = __shfl_down_sync(0xffffffffu, key, o);
        if (ok < key) key = ok;
    }
    if (lane == 0) g_best[row] = key;
}

// ---------------------------------------------------------------------------
// Kernel D: gather + straight-through output + loss sums, float4-vectorized.
// 512 blocks (2 float4 per thread) measured fastest: two independent load
// chains per thread give the MLP this latency-bound kernel needs.
// Per-element fp32 op chain identical to the scalar (passing) version.
// ---------------------------------------------------------------------------
__global__ void epilogue_kernel(const float* __restrict__ latents,
                                const float* __restrict__ y,
                                const float* __restrict__ codebook,
                                const float* __restrict__ noise,
                                float* __restrict__ out, int nElems) {
    double s0 = 0.0, s1 = 0.0, s2 = 0.0;
    const int nVec = nElems >> 2;
    int stride = gridDim.x * blockDim.x;
    for (int v = blockIdx.x * blockDim.x + threadIdx.x; v < nVec; v += stride) {
        int e = v << 2;
        int i = e >> 6, c = e & 63;
        float4 lat = *reinterpret_cast<const float4*>(latents + e);
        float4 yv  = *reinterpret_cast<const float4*>(y + e);
        int kd = (int)(g_best[i] & 0xffffffffull);
        int off = (int)rintf(__fmul_rn(noise[i], 0.5f));
        int kn = kd + off;
        kn = kn < 0 ? 0 : (kn > O_CODES - 1 ? O_CODES - 1 : kn);
        float4 qd = *reinterpret_cast<const float4*>(codebook + (kd << 6) + c);
        float4 qn = *reinterpret_cast<const float4*>(codebook + (kn << 6) + c);
        float4 ov;
        {
            float diff, r, cm;
            diff = __fsub_rn(qn.x, lat.x); ov.x = __fadd_rn(lat.x, diff);
            r = __fsub_rn(ov.x, yv.x); cm = __fsub_rn(lat.x, qd.x);
            s0 += (double)r * r; s1 += (double)cm * cm; s2 += (double)diff * diff;
            diff = __fsub_rn(qn.y, lat.y); ov.y = __fadd_rn(lat.y, diff);
            r = __fsub_rn(ov.y, yv.y); cm = __fsub_rn(lat.y, qd.y);
            s0 += (double)r * r; s1 += (double)cm * cm; s2 += (double)diff * diff;
            diff = __fsub_rn(qn.z, lat.z); ov.z = __fadd_rn(lat.z, diff);
            r = __fsub_rn(ov.z, yv.z); cm = __fsub_rn(lat.z, qd.z);
            s0 += (double)r * r; s1 += (double)cm * cm; s2 += (double)diff * diff;
            diff = __fsub_rn(qn.w, lat.w); ov.w = __fadd_rn(lat.w, diff);
            r = __fsub_rn(ov.w, yv.w); cm = __fsub_rn(lat.w, qd.w);
            s0 += (double)r * r; s1 += (double)cm * cm; s2 += (double)diff * diff;
        }
        *reinterpret_cast<float4*>(out + e) = ov;
    }
    #pragma unroll
    for (int o = 16; o > 0; o >>= 1) {
        s0 += __shfl_down_sync(0xffffffffu, s0, o);
        s1 += __shfl_down_sync(0xffffffffu, s1, o);
        s2 += __shfl_down_sync(0xffffffffu, s2, o);
    }
    if ((threadIdx.x & 31) == 0) {
        atomicAdd(&g_acc[0], s0);
        atomicAdd(&g_acc[1], s1);
        atomicAdd(&g_acc[2], s2);
    }
}

__global__ void finish_kernel(float* __restrict__ out, int lossStart, int lossEnd) {
    double n = (double)N_ROWS * (double)C_DIM;
    float loss = (float)(g_acc[0] / n + 0.25 * (g_acc[1] / n) + g_acc[2] / n);
    for (int i = lossStart + (int)threadIdx.x; i < lossEnd; i += blockDim.x) out[i] = loss;
}

// ---------------------------------------------------------------------------
extern "C" void kernel_launch(void* const* d_in, const int* in_sizes, int n_in,
                              void* d_out, int out_size) {
    const float* latents  = (const float*)d_in[0];
    const float* y        = (const float*)d_in[1];
    const float* codebook = (const float*)d_in[2];
    const float* noise    = (const float*)d_in[3];
    float* out = (float*)d_out;
    int nElems = in_sizes[0];   // 1048576

    cudaFuncSetAttribute(sweep_kernel,
                         cudaFuncAttributeMaxDynamicSharedMemorySize, SMEM_TOTAL);

    prep_kernel<<<(N_ROWS + O_CODES + 255) / 256, 256>>>(latents, codebook);
    dim3 sg(N_ROWS / MROWS, KSPLIT);
    sweep_kernel<<<sg, THREADS, SMEM_TOTAL>>>();
    pass2_kernel<<<N_ROWS / 8, 256>>>(latents, codebook);
    epilogue_kernel<<<512, 256>>>(latents, y, codebook, noise, out, nElems);
    if (out_size > nElems) finish_kernel<<<1, 32>>>(out, nElems, out_size);
}